// round 11
// baseline (speedup 1.0000x reference)
#include <cuda_runtime.h>
#include <cstdint>

#define BB 8
#define LL 256
#define DD 512
#define HH 512
#define NTOT (LL*BB*LL)          // 524288

typedef unsigned int u32;
typedef unsigned long long u64;

// Scratch: transposed projections dl_t[b][h][i], dr_t[b][h][i]
__device__ float g_dlt[BB*HH*LL];
__device__ float g_drt[BB*HH*LL];

// ---------------------------------------------------------------------------
// tf32 helpers
// ---------------------------------------------------------------------------
__device__ __forceinline__ u32 tf32_bits(float f) {
    u32 u; asm("cvt.rna.tf32.f32 %0, %1;" : "=r"(u) : "f"(f)); return u;
}
__device__ __forceinline__ u64 split_pack(float v) {
    const u32 hb = tf32_bits(v);
    const u32 lb = tf32_bits(v - __uint_as_float(hb));
    return (u64)hb | ((u64)lb << 32);
}

__device__ __forceinline__ void mma_k8(float* d,
                                       u32 a0, u32 a1, u32 a2, u32 a3,
                                       u32 b0, u32 b1) {
    asm volatile(
        "mma.sync.aligned.m16n8k8.row.col.f32.tf32.tf32.f32 "
        "{%0,%1,%2,%3}, {%4,%5,%6,%7}, {%8,%9}, {%0,%1,%2,%3};"
        : "+f"(d[0]), "+f"(d[1]), "+f"(d[2]), "+f"(d[3])
        : "r"(a0), "r"(a1), "r"(a2), "r"(a3), "r"(b0), "r"(b1));
}

// 3xTF32: hi*hi + hi*lo + lo*hi
__device__ __forceinline__ void mma3(float* d,
                                     u32 a0h, u32 a1h, u32 a2h, u32 a3h,
                                     u32 a0l, u32 a1l, u32 a2l, u32 a3l,
                                     u64 B0, u64 B1) {
    const u32 b0h = (u32)B0, b0l = (u32)(B0 >> 32);
    const u32 b1h = (u32)B1, b1l = (u32)(B1 >> 32);
    mma_k8(d, a0h, a1h, a2h, a3h, b0h, b1h);
    mma_k8(d, a0h, a1h, a2h, a3h, b0l, b1l);
    mma_k8(d, a0l, a1l, a2l, a3l, b0h, b1h);
}

// ---------------------------------------------------------------------------
// Kernel 1: dual GEMM on tensor cores (3xTF32).
//   dl_t[b,h,i] = sum_k enc[b,i,k]*Wl[k,h];  dr_t likewise.
// CTA: 64i x 64h tile, one b. 8 warps: warp w -> i-block (w&3)*16,
// h-block (w>>2)*32 (4 m16n8 frags per matrix). K chunks of 32.
// smem rows padded to 65 u64 for conflict-free fragment loads.
// ---------------------------------------------------------------------------
#define SROW 65
#define SMAT (32*SROW)           // u64 elements per operand buffer

__global__ __launch_bounds__(256) void dual_gemm_mma(
    const float* __restrict__ enc,
    const float* __restrict__ Wl,
    const float* __restrict__ Wr)
{
    extern __shared__ u64 sm64[];
    u64* sA  = sm64;             // [k][i]  enc   (hi,lo) packed
    u64* sBL = sm64 + SMAT;      // [k][h]  Wl
    u64* sBR = sm64 + 2*SMAT;    // [k][h]  Wr

    const int b  = blockIdx.z;
    const int h0 = blockIdx.x * 64;
    const int i0 = blockIdx.y * 64;

    const int tid  = threadIdx.x;
    const int w    = tid >> 5;
    const int lane = tid & 31;
    const int wi   = w & 3;          // i 16-block
    const int wh   = w >> 2;         // h 32-block
    const int tg   = lane & 3;       // t%4
    const int gi   = lane >> 2;      // t/4

    float accL[4][4], accR[4][4];
#pragma unroll
    for (int f = 0; f < 4; f++)
#pragma unroll
        for (int c = 0; c < 4; c++) { accL[f][c] = 0.f; accR[f][c] = 0.f; }

    // staging indices
    const int ii = tid & 63;         // enc row
    const int kg = tid >> 6;         // 0..3 -> 8 k each
    const int whh = (tid & 15) << 2; // W h offset (4 cols)
    const int wkk = tid >> 4;        // 0..15 -> rows kk, kk+16

    for (int kc = 0; kc < DD; kc += 32) {
        // ---- stage enc (64i x 32k) ----
        {
            const float* ep = &enc[(b * LL + i0 + ii) * DD + kc + kg * 8];
            const float4 v0 = *(const float4*)ep;
            const float4 v1 = *(const float4*)(ep + 4);
            float vv[8] = {v0.x, v0.y, v0.z, v0.w, v1.x, v1.y, v1.z, v1.w};
#pragma unroll
            for (int j = 0; j < 8; j++)
                sA[(kg * 8 + j) * SROW + ii] = split_pack(vv[j]);
        }
        // ---- stage Wl/Wr (32k x 64h) ----
#pragma unroll
        for (int r = 0; r < 2; r++) {
            const int kk = wkk + r * 16;
            const float4 vl = *(const float4*)&Wl[(kc + kk) * HH + h0 + whh];
            const float4 vr = *(const float4*)&Wr[(kc + kk) * HH + h0 + whh];
            u64* dl = &sBL[kk * SROW + whh];
            u64* dr = &sBR[kk * SROW + whh];
            dl[0] = split_pack(vl.x); dl[1] = split_pack(vl.y);
            dl[2] = split_pack(vl.z); dl[3] = split_pack(vl.w);
            dr[0] = split_pack(vr.x); dr[1] = split_pack(vr.y);
            dr[2] = split_pack(vr.z); dr[3] = split_pack(vr.w);
        }
        __syncthreads();

        // ---- 4 mma k-steps of 8 ----
#pragma unroll
        for (int ks = 0; ks < 4; ks++) {
            const u64* Ar = &sA[(ks * 8 + tg) * SROW + (wi << 4) + gi];
            const u64 A0 = Ar[0];
            const u64 A1 = Ar[8];
            const u64 A2 = Ar[4 * SROW];
            const u64 A3 = Ar[4 * SROW + 8];
            const u32 a0h = (u32)A0, a0l = (u32)(A0 >> 32);
            const u32 a1h = (u32)A1, a1l = (u32)(A1 >> 32);
            const u32 a2h = (u32)A2, a2l = (u32)(A2 >> 32);
            const u32 a3h = (u32)A3, a3l = (u32)(A3 >> 32);

            const u64* BLr = &sBL[(ks * 8 + tg) * SROW + (wh << 5) + gi];
            const u64* BRr = &sBR[(ks * 8 + tg) * SROW + (wh << 5) + gi];
#pragma unroll
            for (int f = 0; f < 4; f++) {
                const u64 B0 = BLr[f * 8];
                const u64 B1 = BLr[4 * SROW + f * 8];
                mma3(accL[f], a0h, a1h, a2h, a3h, a0l, a1l, a2l, a3l, B0, B1);
                const u64 C0 = BRr[f * 8];
                const u64 C1 = BRr[4 * SROW + f * 8];
                mma3(accR[f], a0h, a1h, a2h, a3h, a0l, a1l, a2l, a3l, C0, C1);
            }
        }
        __syncthreads();
    }

    // ---- store transposed: g[(b*HH + h)*LL + i] ----
    // c0:(i, h) c1:(i, h+1) c2:(i+8, h) c3:(i+8, h+1)
    const int i_loc = i0 + (wi << 4) + gi;
    const int h_base = h0 + (wh << 5) + tg * 2;
#pragma unroll
    for (int f = 0; f < 4; f++) {
        const long base = (long)(b * HH + h_base + f * 8) * LL + i_loc;
        g_dlt[base]          = accL[f][0];
        g_dlt[base + LL]     = accL[f][1];
        g_dlt[base + 8]      = accL[f][2];
        g_dlt[base + LL + 8] = accL[f][3];
        g_drt[base]          = accR[f][0];
        g_drt[base + LL]     = accR[f][1];
        g_drt[base + 8]      = accR[f][2];
        g_drt[base + LL + 8] = accR[f][3];
    }
}

// ---------------------------------------------------------------------------
// Threefry2x32, key (0, 42), partitionable path: counter = (0, m),
// output bits = lane0 ^ lane1.
// ---------------------------------------------------------------------------
__device__ __forceinline__ unsigned threefry_bits_partitionable(unsigned m)
{
    const unsigned k0 = 0u, k1 = 42u;
    const unsigned k2 = 0x1BD11BDAu ^ k0 ^ k1;
    unsigned x0 = 0u + k0;
    unsigned x1 = m  + k1;
#define TF_RND(r) { x0 += x1; x1 = __funnelshift_l(x1, x1, r); x1 ^= x0; }
    TF_RND(13) TF_RND(15) TF_RND(26) TF_RND(6)   x0 += k1; x1 += k2 + 1u;
    TF_RND(17) TF_RND(29) TF_RND(16) TF_RND(24)  x0 += k2; x1 += k0 + 2u;
    TF_RND(13) TF_RND(15) TF_RND(26) TF_RND(6)   x0 += k0; x1 += k1 + 3u;
    TF_RND(17) TF_RND(29) TF_RND(16) TF_RND(24)  x0 += k1; x1 += k2 + 4u;
    TF_RND(13) TF_RND(15) TF_RND(26) TF_RND(6)   x0 += k2; x1 += k0 + 5u;
#undef TF_RND
    return x0 ^ x1;
}

__device__ __forceinline__ float tanh_fast(float x)
{
    float y;
    asm("tanh.approx.f32 %0, %1;" : "=f"(y) : "f"(x));
    return y;
}

// ---------------------------------------------------------------------------
// Kernel 2: biaffine + epilogue (round-7 version, unchanged).
// 32i x 16j tile per CTA -> 1024 CTAs.
// ---------------------------------------------------------------------------
__global__ __launch_bounds__(256) void biaffine_kernel(
    const float* __restrict__ U,
    const float* __restrict__ logit_bias,
    float* __restrict__ out)
{
    const int b  = blockIdx.z;
    const int i0 = blockIdx.y * 32;
    const int j0 = blockIdx.x * 16;

    __shared__ float sl[32][32];   // [h][i]
    __shared__ float sr[32][16];   // [h][j]
    __shared__ float su[32];

    const int tid = threadIdx.x;
    const int tx  = tid & 15;      // j (1 each)
    const int ty  = tid >> 4;      // i group (2 each)

    float acc[2] = {0.f, 0.f};

    for (int h0 = 0; h0 < HH; h0 += 32) {
        {
            int hk  = tid >> 3;             // 0..31
            int col = (tid & 7) << 2;       // 0..28
            *(float4*)&sl[hk][col] = *(const float4*)&g_dlt[(b * HH + h0 + hk) * LL + i0 + col];
        }
        if (tid < 128) {
            int hk  = tid >> 2;             // 0..31
            int col = (tid & 3) << 2;       // 0..12
            *(float4*)&sr[hk][col] = *(const float4*)&g_drt[(b * HH + h0 + hk) * LL + j0 + col];
        }
        if (tid < 32) su[tid] = U[h0 + tid];
        __syncthreads();

#pragma unroll
        for (int hk = 0; hk < 32; hk++) {
            float dl[2];
            *(float2*)dl = *(const float2*)&sl[hk][ty << 1];
            const float dr = sr[hk][tx];
            const float u  = su[hk];
            acc[0] = fmaf(u, tanh_fast(dl[0] + dr), acc[0]);
            acc[1] = fmaf(u, tanh_fast(dl[1] + dr), acc[1]);
        }
        __syncthreads();
    }

    const float lb = logit_bias[0];

#pragma unroll
    for (int a = 0; a < 2; a++) {
        const int i = i0 + (ty << 1) + a;
        const int j = j0 + tx;
        float x = acc[a] + lb;
        if (i == j) x -= 1e8f;

        const int m = i * (BB * LL) + b * LL + j;   // [L,B,L] flat index

        // mask_scores
        out[NTOT + m] = x;

        // p = sigmoid(x)
        const float p = 1.0f / (1.0f + expf(-x));

        // entropy = p*softplus(-x) + (1-p)*softplus(x)
        const float e  = expf(-fabsf(x));
        const float l1 = log1pf(e);
        const float sp_pos = fmaxf(x, 0.f) + l1;   // softplus(x)
        const float sp_neg = fmaxf(-x, 0.f) + l1;  // softplus(-x)
        out[2 * NTOT + m] = p * sp_neg + (1.0f - p) * sp_pos;

        // bernoulli sample, JAX partitionable threefry (key=42)
        const unsigned bits = threefry_bits_partitionable((unsigned)m);
        const float u01 = __uint_as_float((bits >> 9) | 0x3f800000u) - 1.0f;
        out[m] = (u01 < p) ? 1.0f : 0.0f;
    }
}

// ---------------------------------------------------------------------------
extern "C" void kernel_launch(void* const* d_in, const int* in_sizes, int n_in,
                              void* d_out, int out_size)
{
    const float* enc  = (const float*)d_in[0];
    const float* Wl   = (const float*)d_in[1];
    const float* Wr   = (const float*)d_in[2];
    const float* U    = (const float*)d_in[3];
    const float* bias = (const float*)d_in[4];
    float* out = (float*)d_out;

    const int smem_bytes = 3 * SMAT * sizeof(u64);   // 49920
    static bool attr_set = false;
    if (!attr_set) {
        cudaFuncSetAttribute(dual_gemm_mma,
                             cudaFuncAttributeMaxDynamicSharedMemorySize, smem_bytes);
        attr_set = true;
    }

    dim3 g1(HH / 64, LL / 64, BB);   // 8 x 4 x 8 = 256 CTAs
    dual_gemm_mma<<<g1, 256, smem_bytes>>>(enc, Wl, Wr);

    dim3 g2(LL / 16, LL / 32, BB);   // 16 x 8 x 8 = 1024 CTAs
    biaffine_kernel<<<g2, 256>>>(U, bias, out);
}

// round 12
// speedup vs baseline: 1.4972x; 1.4972x over previous
#include <cuda_runtime.h>
#include <cstdint>

#define BB 8
#define LL 256
#define DD 512
#define HH 512
#define NTOT (LL*BB*LL)          // 524288

// Scratch: transposed projections dl_t[b][h][i], dr_t[b][h][i]
__device__ float g_dlt[BB*HH*LL];
__device__ float g_drt[BB*HH*LL];

// ---------------------------------------------------------------------------
// f32x2 packed-math helpers
// ---------------------------------------------------------------------------
typedef unsigned long long u64;

__device__ __forceinline__ u64 pack2(float lo, float hi) {
    u64 r; asm("mov.b64 %0, {%1, %2};" : "=l"(r) : "f"(lo), "f"(hi)); return r;
}
__device__ __forceinline__ void unpack2(u64 v, float& lo, float& hi) {
    asm("mov.b64 {%0, %1}, %2;" : "=f"(lo), "=f"(hi) : "l"(v));
}
__device__ __forceinline__ void ffma2(u64& d, u64 a, u64 b) {
    asm("fma.rn.f32x2 %0, %1, %2, %0;" : "+l"(d) : "l"(a), "l"(b));
}

// ---------------------------------------------------------------------------
// Kernel 1: fused dual GEMM (round-7 version — at the FFMA floor).
// Block: 64h x 64i tile for one b. 256 threads.
// ---------------------------------------------------------------------------
__global__ __launch_bounds__(256) void dual_gemm_kernel(
    const float* __restrict__ enc,
    const float* __restrict__ Wl,
    const float* __restrict__ Wr)
{
    const int b  = blockIdx.z;
    const int h0 = blockIdx.x * 64;
    const int i0 = blockIdx.y * 64;

    __shared__ float se[16][68];   // [k][i] (padded)
    __shared__ float swl[16][64];  // [k][h]
    __shared__ float swr[16][64];

    const int tid = threadIdx.x;
    const int tx  = tid & 15;      // h group (4 h each)
    const int ty  = tid >> 4;      // i group (4 i each)

    u64 accl2[4][2], accr2[4][2];  // [a=i][h-pair]
#pragma unroll
    for (int a = 0; a < 4; a++)
#pragma unroll
        for (int c2 = 0; c2 < 2; c2++) { accl2[a][c2] = 0ull; accr2[a][c2] = 0ull; }

    for (int k0 = 0; k0 < DD; k0 += 16) {
        {
            int kk = tid >> 4;          // 0..15
            int hh = (tid & 15) << 2;   // 0..60
            const float4 vl = *(const float4*)&Wl[(k0 + kk) * HH + h0 + hh];
            const float4 vr = *(const float4*)&Wr[(k0 + kk) * HH + h0 + hh];
            *(float4*)&swl[kk][hh] = vl;
            *(float4*)&swr[kk][hh] = vr;
        }
        {
            int ii = tid >> 2;          // 0..63
            int kk = (tid & 3) << 2;    // 0,4,8,12
            const float4 v = *(const float4*)&enc[(b * LL + i0 + ii) * DD + k0 + kk];
            se[kk + 0][ii] = v.x;
            se[kk + 1][ii] = v.y;
            se[kk + 2][ii] = v.z;
            se[kk + 3][ii] = v.w;
        }
        __syncthreads();

#pragma unroll
        for (int kk = 0; kk < 16; kk++) {
            float ev[4];
            *(float4*)ev = *(const float4*)&se[kk][ty << 2];
            const u64 wl01 = *(const u64*)&swl[kk][tx << 2];
            const u64 wl23 = *(const u64*)&swl[kk][(tx << 2) + 2];
            const u64 wr01 = *(const u64*)&swr[kk][tx << 2];
            const u64 wr23 = *(const u64*)&swr[kk][(tx << 2) + 2];
#pragma unroll
            for (int a = 0; a < 4; a++) {
                const u64 ea = pack2(ev[a], ev[a]);
                ffma2(accl2[a][0], ea, wl01);
                ffma2(accl2[a][1], ea, wl23);
                ffma2(accr2[a][0], ea, wr01);
                ffma2(accr2[a][1], ea, wr23);
            }
        }
        __syncthreads();
    }

#pragma unroll
    for (int c2 = 0; c2 < 2; c2++) {
        float l0[4], l1[4], r0[4], r1[4];
#pragma unroll
        for (int a = 0; a < 4; a++) {
            unpack2(accl2[a][c2], l0[a], l1[a]);
            unpack2(accr2[a][c2], r0[a], r1[a]);
        }
        const int h    = h0 + (tx << 2) + (c2 << 1);
        const int base = (b * HH + h) * LL + i0 + (ty << 2);
        *(float4*)&g_dlt[base]      = make_float4(l0[0], l0[1], l0[2], l0[3]);
        *(float4*)&g_dlt[base + LL] = make_float4(l1[0], l1[1], l1[2], l1[3]);
        *(float4*)&g_drt[base]      = make_float4(r0[0], r0[1], r0[2], r0[3]);
        *(float4*)&g_drt[base + LL] = make_float4(r1[0], r1[1], r1[2], r1[3]);
    }
}

// ---------------------------------------------------------------------------
// Threefry2x32, key (0, 42), partitionable path: counter = (0, m),
// output bits = lane0 ^ lane1.
// ---------------------------------------------------------------------------
__device__ __forceinline__ unsigned threefry_bits_partitionable(unsigned m)
{
    const unsigned k0 = 0u, k1 = 42u;
    const unsigned k2 = 0x1BD11BDAu ^ k0 ^ k1;
    unsigned x0 = 0u + k0;
    unsigned x1 = m  + k1;
#define TF_RND(r) { x0 += x1; x1 = __funnelshift_l(x1, x1, r); x1 ^= x0; }
    TF_RND(13) TF_RND(15) TF_RND(26) TF_RND(6)   x0 += k1; x1 += k2 + 1u;
    TF_RND(17) TF_RND(29) TF_RND(16) TF_RND(24)  x0 += k2; x1 += k0 + 2u;
    TF_RND(13) TF_RND(15) TF_RND(26) TF_RND(6)   x0 += k0; x1 += k1 + 3u;
    TF_RND(17) TF_RND(29) TF_RND(16) TF_RND(24)  x0 += k1; x1 += k2 + 4u;
    TF_RND(13) TF_RND(15) TF_RND(26) TF_RND(6)   x0 += k2; x1 += k0 + 5u;
#undef TF_RND
    return x0 ^ x1;
}

__device__ __forceinline__ float tanh_fast(float x)
{
    float y;
    asm("tanh.approx.f32 %0, %1;" : "=f"(y) : "f"(x));
    return y;
}

// ---------------------------------------------------------------------------
// Kernel 2: biaffine + epilogue. 32i x 16j tile per CTA -> 1024 CTAs.
// Round-7 math, with: (a) next-chunk register prefetch so the global-load
// latency hides under the 32-hk MUFU compute; (b) U staged to smem once.
// Accumulation order unchanged -> logits bit-identical to round 7.
// ---------------------------------------------------------------------------
__global__ __launch_bounds__(256) void biaffine_kernel(
    const float* __restrict__ U,
    const float* __restrict__ logit_bias,
    float* __restrict__ out)
{
    const int b  = blockIdx.z;
    const int i0 = blockIdx.y * 32;
    const int j0 = blockIdx.x * 16;

    __shared__ float sl[32][32];   // [h][i]
    __shared__ float sr[32][16];   // [h][j]
    __shared__ float su[HH];       // all 512 U values, staged once

    const int tid = threadIdx.x;
    const int tx  = tid & 15;      // j (1 each)
    const int ty  = tid >> 4;      // i group (2 each)

    // staging indices
    const int lhk  = tid >> 3;             // 0..31
    const int lcol = (tid & 7) << 2;       // 0..28
    const int rhk  = tid >> 2;             // 0..31 (tid<128)
    const int rcol = (tid & 3) << 2;       // 0..12

    // stage all of U once (covered by the first loop-top barrier)
    for (int idx = tid; idx < HH; idx += 256) su[idx] = U[idx];

    // preload chunk 0
    float4 pl = *(const float4*)&g_dlt[(b * HH + lhk) * LL + i0 + lcol];
    float4 pr;
    if (tid < 128) pr = *(const float4*)&g_drt[(b * HH + rhk) * LL + j0 + rcol];

    float acc[2] = {0.f, 0.f};

    for (int h0 = 0; h0 < HH; h0 += 32) {
        *(float4*)&sl[lhk][lcol] = pl;
        if (tid < 128) *(float4*)&sr[rhk][rcol] = pr;
        __syncthreads();

        // issue next chunk's loads now; latency hides under the compute below
        if (h0 + 32 < HH) {
            pl = *(const float4*)&g_dlt[(b * HH + h0 + 32 + lhk) * LL + i0 + lcol];
            if (tid < 128)
                pr = *(const float4*)&g_drt[(b * HH + h0 + 32 + rhk) * LL + j0 + rcol];
        }

#pragma unroll
        for (int hk = 0; hk < 32; hk++) {
            float dl[2];
            *(float2*)dl = *(const float2*)&sl[hk][ty << 1];
            const float dr = sr[hk][tx];
            const float u  = su[h0 + hk];
            acc[0] = fmaf(u, tanh_fast(dl[0] + dr), acc[0]);
            acc[1] = fmaf(u, tanh_fast(dl[1] + dr), acc[1]);
        }
        __syncthreads();
    }

    const float lb = logit_bias[0];

#pragma unroll
    for (int a = 0; a < 2; a++) {
        const int i = i0 + (ty << 1) + a;
        const int j = j0 + tx;
        float x = acc[a] + lb;
        if (i == j) x -= 1e8f;

        const int m = i * (BB * LL) + b * LL + j;   // [L,B,L] flat index

        // mask_scores
        out[NTOT + m] = x;

        // p = sigmoid(x)
        const float p = 1.0f / (1.0f + expf(-x));

        // entropy = p*softplus(-x) + (1-p)*softplus(x)
        const float e  = expf(-fabsf(x));
        const float l1 = log1pf(e);
        const float sp_pos = fmaxf(x, 0.f) + l1;   // softplus(x)
        const float sp_neg = fmaxf(-x, 0.f) + l1;  // softplus(-x)
        out[2 * NTOT + m] = p * sp_neg + (1.0f - p) * sp_pos;

        // bernoulli sample, JAX partitionable threefry (key=42)
        const unsigned bits = threefry_bits_partitionable((unsigned)m);
        const float u01 = __uint_as_float((bits >> 9) | 0x3f800000u) - 1.0f;
        out[m] = (u01 < p) ? 1.0f : 0.0f;
    }
}

// ---------------------------------------------------------------------------
extern "C" void kernel_launch(void* const* d_in, const int* in_sizes, int n_in,
                              void* d_out, int out_size)
{
    const float* enc  = (const float*)d_in[0];
    const float* Wl   = (const float*)d_in[1];
    const float* Wr   = (const float*)d_in[2];
    const float* U    = (const float*)d_in[3];
    const float* bias = (const float*)d_in[4];
    float* out = (float*)d_out;

    dim3 g1(HH / 64, LL / 64, BB);   // 8 x 4 x 8 = 256 CTAs
    dual_gemm_kernel<<<g1, 256>>>(enc, Wl, Wr);

    dim3 g2(LL / 16, LL / 32, BB);   // 16 x 8 x 8 = 1024 CTAs
    biaffine_kernel<<<g2, 256>>>(U, bias, out);
}

// round 13
// speedup vs baseline: 1.5629x; 1.0439x over previous
#include <cuda_runtime.h>
#include <cstdint>

#define BB 8
#define LL 256
#define DD 512
#define HH 512
#define NTOT (LL*BB*LL)          // 524288

// Scratch: transposed projections dl_t[b][h][i], dr_t[b][h][i]
__device__ float g_dlt[BB*HH*LL];
__device__ float g_drt[BB*HH*LL];

// ---------------------------------------------------------------------------
// f32x2 packed-math helpers
// ---------------------------------------------------------------------------
typedef unsigned long long u64;

__device__ __forceinline__ u64 pack2(float lo, float hi) {
    u64 r; asm("mov.b64 %0, {%1, %2};" : "=l"(r) : "f"(lo), "f"(hi)); return r;
}
__device__ __forceinline__ void unpack2(u64 v, float& lo, float& hi) {
    asm("mov.b64 {%0, %1}, %2;" : "=f"(lo), "=f"(hi) : "l"(v));
}
__device__ __forceinline__ void ffma2(u64& d, u64 a, u64 b) {
    asm("fma.rn.f32x2 %0, %1, %2, %0;" : "+l"(d) : "l"(a), "l"(b));
}

// ---------------------------------------------------------------------------
// Kernel 1: fused dual GEMM. Round-7 math (identical ffma2 order), now with
// double-buffered smem + register prefetch: ONE sync per k-chunk, global-load
// latency hidden under the 16-kk compute block.
// Block: 64h x 64i tile for one b. 256 threads.
// ---------------------------------------------------------------------------
__global__ __launch_bounds__(256) void dual_gemm_kernel(
    const float* __restrict__ enc,
    const float* __restrict__ Wl,
    const float* __restrict__ Wr)
{
    const int b  = blockIdx.z;
    const int h0 = blockIdx.x * 64;
    const int i0 = blockIdx.y * 64;

    __shared__ float se[2][16][68];   // [buf][k][i] (padded)
    __shared__ float swl[2][16][64];  // [buf][k][h]
    __shared__ float swr[2][16][64];

    const int tid = threadIdx.x;
    const int tx  = tid & 15;      // h group (4 h each)
    const int ty  = tid >> 4;      // i group (4 i each)

    // staging indices
    const int kkW = tid >> 4;          // 0..15  W row
    const int hhW = (tid & 15) << 2;   // 0..60
    const int iiE = tid >> 2;          // 0..63  enc row
    const int kkE = (tid & 3) << 2;    // 0,4,8,12

    u64 accl2[4][2], accr2[4][2];  // [a=i][h-pair]
#pragma unroll
    for (int a = 0; a < 4; a++)
#pragma unroll
        for (int c2 = 0; c2 < 2; c2++) { accl2[a][c2] = 0ull; accr2[a][c2] = 0ull; }

    // preload chunk 0 into registers
    float4 pvl = *(const float4*)&Wl[kkW * HH + h0 + hhW];
    float4 pvr = *(const float4*)&Wr[kkW * HH + h0 + hhW];
    float4 pve = *(const float4*)&enc[(b * LL + i0 + iiE) * DD + kkE];

    int p = 0;
    for (int k0 = 0; k0 < DD; k0 += 16, p ^= 1) {
        // store prefetched chunk into buffer p
        *(float4*)&swl[p][kkW][hhW] = pvl;
        *(float4*)&swr[p][kkW][hhW] = pvr;
        se[p][kkE + 0][iiE] = pve.x;
        se[p][kkE + 1][iiE] = pve.y;
        se[p][kkE + 2][iiE] = pve.z;
        se[p][kkE + 3][iiE] = pve.w;

        // issue next chunk's loads; latency hides under compute below
        if (k0 + 16 < DD) {
            pvl = *(const float4*)&Wl[(k0 + 16 + kkW) * HH + h0 + hhW];
            pvr = *(const float4*)&Wr[(k0 + 16 + kkW) * HH + h0 + hhW];
            pve = *(const float4*)&enc[(b * LL + i0 + iiE) * DD + k0 + 16 + kkE];
        }

        __syncthreads();   // single barrier: stores(p) visible; compute(p-2) done

#pragma unroll
        for (int kk = 0; kk < 16; kk++) {
            float ev[4];
            *(float4*)ev = *(const float4*)&se[p][kk][ty << 2];
            const u64 wl01 = *(const u64*)&swl[p][kk][tx << 2];
            const u64 wl23 = *(const u64*)&swl[p][kk][(tx << 2) + 2];
            const u64 wr01 = *(const u64*)&swr[p][kk][tx << 2];
            const u64 wr23 = *(const u64*)&swr[p][kk][(tx << 2) + 2];
#pragma unroll
            for (int a = 0; a < 4; a++) {
                const u64 ea = pack2(ev[a], ev[a]);
                ffma2(accl2[a][0], ea, wl01);
                ffma2(accl2[a][1], ea, wl23);
                ffma2(accr2[a][0], ea, wr01);
                ffma2(accr2[a][1], ea, wr23);
            }
        }
    }

#pragma unroll
    for (int c2 = 0; c2 < 2; c2++) {
        float l0[4], l1[4], r0[4], r1[4];
#pragma unroll
        for (int a = 0; a < 4; a++) {
            unpack2(accl2[a][c2], l0[a], l1[a]);
            unpack2(accr2[a][c2], r0[a], r1[a]);
        }
        const int h    = h0 + (tx << 2) + (c2 << 1);
        const int base = (b * HH + h) * LL + i0 + (ty << 2);
        *(float4*)&g_dlt[base]      = make_float4(l0[0], l0[1], l0[2], l0[3]);
        *(float4*)&g_dlt[base + LL] = make_float4(l1[0], l1[1], l1[2], l1[3]);
        *(float4*)&g_drt[base]      = make_float4(r0[0], r0[1], r0[2], r0[3]);
        *(float4*)&g_drt[base + LL] = make_float4(r1[0], r1[1], r1[2], r1[3]);
    }
}

// ---------------------------------------------------------------------------
// Threefry2x32, key (0, 42), partitionable path: counter = (0, m),
// output bits = lane0 ^ lane1.
// ---------------------------------------------------------------------------
__device__ __forceinline__ unsigned threefry_bits_partitionable(unsigned m)
{
    const unsigned k0 = 0u, k1 = 42u;
    const unsigned k2 = 0x1BD11BDAu ^ k0 ^ k1;
    unsigned x0 = 0u + k0;
    unsigned x1 = m  + k1;
#define TF_RND(r) { x0 += x1; x1 = __funnelshift_l(x1, x1, r); x1 ^= x0; }
    TF_RND(13) TF_RND(15) TF_RND(26) TF_RND(6)   x0 += k1; x1 += k2 + 1u;
    TF_RND(17) TF_RND(29) TF_RND(16) TF_RND(24)  x0 += k2; x1 += k0 + 2u;
    TF_RND(13) TF_RND(15) TF_RND(26) TF_RND(6)   x0 += k0; x1 += k1 + 3u;
    TF_RND(17) TF_RND(29) TF_RND(16) TF_RND(24)  x0 += k1; x1 += k2 + 4u;
    TF_RND(13) TF_RND(15) TF_RND(26) TF_RND(6)   x0 += k2; x1 += k0 + 5u;
#undef TF_RND
    return x0 ^ x1;
}

__device__ __forceinline__ float tanh_fast(float x)
{
    float y;
    asm("tanh.approx.f32 %0, %1;" : "=f"(y) : "f"(x));
    return y;
}

// ---------------------------------------------------------------------------
// Kernel 2: biaffine + epilogue (round-12 version) with minBlocks=8 so all
// 1024 CTAs are wave-1 resident (no MUFU-starved drain tail).
// 32i x 16j tile per CTA -> 1024 CTAs. Math bit-identical to round 12.
// ---------------------------------------------------------------------------
__global__ __launch_bounds__(256, 8) void biaffine_kernel(
    const float* __restrict__ U,
    const float* __restrict__ logit_bias,
    float* __restrict__ out)
{
    const int b  = blockIdx.z;
    const int i0 = blockIdx.y * 32;
    const int j0 = blockIdx.x * 16;

    __shared__ float sl[32][32];   // [h][i]
    __shared__ float sr[32][16];   // [h][j]
    __shared__ float su[HH];       // all 512 U values, staged once

    const int tid = threadIdx.x;
    const int tx  = tid & 15;      // j (1 each)
    const int ty  = tid >> 4;      // i group (2 each)

    // staging indices
    const int lhk  = tid >> 3;             // 0..31
    const int lcol = (tid & 7) << 2;       // 0..28
    const int rhk  = tid >> 2;             // 0..31 (tid<128)
    const int rcol = (tid & 3) << 2;       // 0..12

    // stage all of U once (covered by the first loop-top barrier)
    for (int idx = tid; idx < HH; idx += 256) su[idx] = U[idx];

    // preload chunk 0
    float4 pl = *(const float4*)&g_dlt[(b * HH + lhk) * LL + i0 + lcol];
    float4 pr;
    if (tid < 128) pr = *(const float4*)&g_drt[(b * HH + rhk) * LL + j0 + rcol];

    float acc[2] = {0.f, 0.f};

    for (int h0 = 0; h0 < HH; h0 += 32) {
        *(float4*)&sl[lhk][lcol] = pl;
        if (tid < 128) *(float4*)&sr[rhk][rcol] = pr;
        __syncthreads();

        // issue next chunk's loads now; latency hides under the compute below
        if (h0 + 32 < HH) {
            pl = *(const float4*)&g_dlt[(b * HH + h0 + 32 + lhk) * LL + i0 + lcol];
            if (tid < 128)
                pr = *(const float4*)&g_drt[(b * HH + h0 + 32 + rhk) * LL + j0 + rcol];
        }

#pragma unroll
        for (int hk = 0; hk < 32; hk++) {
            float dl[2];
            *(float2*)dl = *(const float2*)&sl[hk][ty << 1];
            const float dr = sr[hk][tx];
            const float u  = su[h0 + hk];
            acc[0] = fmaf(u, tanh_fast(dl[0] + dr), acc[0]);
            acc[1] = fmaf(u, tanh_fast(dl[1] + dr), acc[1]);
        }
        __syncthreads();
    }

    const float lb = logit_bias[0];

#pragma unroll
    for (int a = 0; a < 2; a++) {
        const int i = i0 + (ty << 1) + a;
        const int j = j0 + tx;
        float x = acc[a] + lb;
        if (i == j) x -= 1e8f;

        const int m = i * (BB * LL) + b * LL + j;   // [L,B,L] flat index

        // mask_scores
        out[NTOT + m] = x;

        // p = sigmoid(x)
        const float p = 1.0f / (1.0f + expf(-x));

        // entropy = p*softplus(-x) + (1-p)*softplus(x)
        const float e  = expf(-fabsf(x));
        const float l1 = log1pf(e);
        const float sp_pos = fmaxf(x, 0.f) + l1;   // softplus(x)
        const float sp_neg = fmaxf(-x, 0.f) + l1;  // softplus(-x)
        out[2 * NTOT + m] = p * sp_neg + (1.0f - p) * sp_pos;

        // bernoulli sample, JAX partitionable threefry (key=42)
        const unsigned bits = threefry_bits_partitionable((unsigned)m);
        const float u01 = __uint_as_float((bits >> 9) | 0x3f800000u) - 1.0f;
        out[m] = (u01 < p) ? 1.0f : 0.0f;
    }
}

// ---------------------------------------------------------------------------
extern "C" void kernel_launch(void* const* d_in, const int* in_sizes, int n_in,
                              void* d_out, int out_size)
{
    const float* enc  = (const float*)d_in[0];
    const float* Wl   = (const float*)d_in[1];
    const float* Wr   = (const float*)d_in[2];
    const float* U    = (const float*)d_in[3];
    const float* bias = (const float*)d_in[4];
    float* out = (float*)d_out;

    dim3 g1(HH / 64, LL / 64, BB);   // 8 x 4 x 8 = 256 CTAs
    dual_gemm_kernel<<<g1, 256>>>(enc, Wl, Wr);

    dim3 g2(LL / 16, LL / 32, BB);   // 16 x 8 x 8 = 1024 CTAs
    biaffine_kernel<<<g2, 256>>>(U, bias, out);
}